// round 13
// baseline (speedup 1.0000x reference)
#include <cuda_runtime.h>
#include <cuda_bf16.h>
#include <stdint.h>
#include <math.h>

#define B      512
#define H      512
#define TENC   512
#define TDEC   128
#define TTOT   640
#define GROUP  32            // CTAs per mt barrier group
#define NMT    4
#define NTHREADS 1024

#define ASTAGE_BYTES 32768   // hh 16KB + hl 16KB per pair-stage
#define NASTAGE 3
#define WOFF   (NASTAGE * ASTAGE_BYTES)        // 98304
#define SMEM_DYN (WOFF + 16 * 8192 + 1024)     // 230400 <= 232448

// ---------------- persistent device state (no allocation allowed) ----------
static __device__ __align__(16) __nv_bfloat16 g_hhi0[B * H];
static __device__ __align__(16) __nv_bfloat16 g_hhi1[B * H];
static __device__ __align__(16) __nv_bfloat16 g_hlo0[B * H];
static __device__ __align__(16) __nv_bfloat16 g_hlo1[B * H];
static __device__ float g_xpart[GROUP * B];            // [nt][b] partial lin(h)
static __device__ __align__(16) __nv_bfloat16 g_whi_e[2048 * 512];
static __device__ __align__(16) __nv_bfloat16 g_wlo_e[2048 * 512];
static __device__ __align__(16) __nv_bfloat16 g_whi_d[2048 * 512];
static __device__ __align__(16) __nv_bfloat16 g_wlo_d[2048 * 512];
static __device__ unsigned g_cnt[NMT * 32];            // 128B-spaced counters
static __device__ volatile unsigned g_sense[NMT * 32];

// ---------------- helpers ----------------------------------------------------
__device__ __forceinline__ uint32_t smem_u32(const void* p) {
    uint32_t a;
    asm("{ .reg .u64 t; cvta.to.shared.u64 t, %1; cvt.u32.u64 %0, t; }"
        : "=r"(a) : "l"(p));
    return a;
}
__device__ __forceinline__ void cp16(uint32_t dst, const void* src) {
    asm volatile("cp.async.cg.shared.global [%0], [%1], 16;" :: "r"(dst), "l"(src));
}
__device__ __forceinline__ void cp_commit() {
    asm volatile("cp.async.commit_group;" ::: "memory");
}
__device__ __forceinline__ void cp_wait1() {
    asm volatile("cp.async.wait_group 1;" ::: "memory");
}
__device__ __forceinline__ void cp_wait0() {
    asm volatile("cp.async.wait_group 0;" ::: "memory");
}
__device__ __forceinline__ void ldsm_x4(uint32_t& r0, uint32_t& r1,
                                        uint32_t& r2, uint32_t& r3, uint32_t addr) {
    asm volatile("ldmatrix.sync.aligned.m8n8.x4.shared.b16 {%0,%1,%2,%3}, [%4];"
                 : "=r"(r0), "=r"(r1), "=r"(r2), "=r"(r3) : "r"(addr));
}
__device__ __forceinline__ void mma_bf16(float* c, const uint32_t* a,
                                         uint32_t b0, uint32_t b1) {
    asm volatile(
        "mma.sync.aligned.m16n8k16.row.col.f32.bf16.bf16.f32 "
        "{%0,%1,%2,%3}, {%4,%5,%6,%7}, {%8,%9}, {%0,%1,%2,%3};"
        : "+f"(c[0]), "+f"(c[1]), "+f"(c[2]), "+f"(c[3])
        : "r"(a[0]), "r"(a[1]), "r"(a[2]), "r"(a[3]), "r"(b0), "r"(b1));
}
__device__ __forceinline__ float sigf(float x) { return 1.0f / (1.0f + __expf(-x)); }
__device__ __forceinline__ float tanhe(float x) {
    return __fmaf_rn(2.0f, sigf(2.0f * x), -1.0f);
}

// Sense-reversing barrier across the 32 CTAs of one mt group.
__device__ __forceinline__ void group_barrier(int mt, unsigned want) {
    __syncthreads();
    if (threadIdx.x == 0) {
        __threadfence();                       // release h / xpart writes
        if (atomicAdd(&g_cnt[mt * 32], 1u) == GROUP - 1u) {
            g_cnt[mt * 32] = 0u;
            __threadfence();
            g_sense[mt * 32] = want;
        } else {
            while (g_sense[mt * 32] != want) __nanosleep(32);
        }
        __threadfence();                       // acquire
    }
    __syncthreads();
}

// ---------------- prologue kernels -------------------------------------------
// Repack W (2048,512): packed row n' = nt*64 + g*16 + jl  <->  n = g*512 + nt*16 + jl
__global__ void pack_w_kernel(const float* __restrict__ W,
                              __nv_bfloat16* __restrict__ whi,
                              __nv_bfloat16* __restrict__ wlo) {
    int idx = blockIdx.x * 256 + threadIdx.x;
    int np = idx >> 9, k = idx & 511;
    int nt = np >> 6, r = np & 63;
    int n = (r >> 4) * 512 + nt * 16 + (r & 15);
    float w = W[n * 512 + k];
    __nv_bfloat16 hi = __float2bfloat16_rn(w);
    whi[idx] = hi;
    wlo[idx] = __float2bfloat16_rn(w - __bfloat162float(hi));
}

__global__ void zero_state_kernel() {
    int i = blockIdx.x * 256 + threadIdx.x;
    if (i < B * H) {
        g_hhi0[i] = __float2bfloat16(0.0f);
        g_hlo0[i] = __float2bfloat16(0.0f);
    }
}

// ---------------- the persistent encoder-decoder kernel ----------------------
__global__ void __launch_bounds__(NTHREADS, 1)
lstm_persistent(const float* __restrict__ inputs,
                const __nv_bfloat16* __restrict__ whiE, const __nv_bfloat16* __restrict__ wloE,
                const __nv_bfloat16* __restrict__ whiD, const __nv_bfloat16* __restrict__ wloD,
                const float* __restrict__ encWih, const float* __restrict__ encB,
                const float* __restrict__ decWih, const float* __restrict__ decB,
                const float* __restrict__ linW, const float* __restrict__ linb,
                float* __restrict__ out)
{
    extern __shared__ char dsmem[];
    uint32_t raw = smem_u32(dsmem);
    uint32_t sb  = (raw + 1023) & ~1023u;
    char* sp     = dsmem + (sb - raw);
    float* zs    = (float*)sp;     // 128 x 68 f32 (34 KB), reuses A stages post-drain

    const int tid  = threadIdx.x;
    const int wid  = tid >> 5;
    const int lane = tid & 31;
    const int wm   = wid >> 2;     // 0..7 : 16-row warp tile
    const int wn   = wid & 3;      // 0..3 : 16-col warp tile
    const int nt   = blockIdx.x;   // 0..31
    const int mt   = blockIdx.y;   // 0..3
    const int brow0 = mt * 128;

    // ---- staging map: thread covers 16B in exactly 1 row of a 128x64 chunk --
    const int gr  = tid >> 3;             // 0..127
    const int gce = (tid & 7) * 8;        // element col
    const uint32_t soA = (uint32_t)gr * 128u
        + (((uint32_t)gce * 2) ^ (uint32_t)((gr & 7) << 4));

    // ---- ldmatrix addressing --------------------------------------------------
    const int lrow = lane & 15;
    const uint32_t kb2 = (uint32_t)((lane >> 4) * 16);
    const uint32_t aoff = (uint32_t)(wm * 16 + lrow) * 128u;
    const uint32_t axor = (uint32_t)((lrow & 7) << 4);
    const uint32_t boff = (uint32_t)(wn * 16 + lrow) * 128u;
    const uint32_t bxor = (uint32_t)((lrow & 7) << 4);

    // ---- load W tiles into smem (16 tiles x 8KB: Wh kc0..7, Wl kc0..7) ------
    auto load_w = [&](const __nv_bfloat16* wh, const __nv_bfloat16* wl) {
#pragma unroll 4
        for (int j = 0; j < 8; ++j) {
            int slot = tid + j * NTHREADS;
            int tile = slot >> 9;
            int win  = slot & 511;
            int row  = win >> 3;
            int ce   = (win & 7) * 8;
            const __nv_bfloat16* src = ((tile >> 3) ? wl : wh)
                + (size_t)(nt * 64 + row) * 512 + (tile & 7) * 64 + ce;
            uint32_t dst = sb + WOFF + (uint32_t)tile * 8192u
                + (uint32_t)row * 128u
                + (((uint32_t)ce * 2u) ^ (uint32_t)((row & 7) << 4));
            cp16(dst, src);
        }
        cp_commit();
        cp_wait0();
        __syncthreads();
    };

    load_w(whiE, wloE);
    const float* Wih  = encWih;
    const float* bias = encB;

    // ---- epilogue constants ----------------------------------------------------
    const int q    = tid & 7;             // 8 threads per row
    const int eml  = tid >> 3;            // 0..127 (batch row in tile)
    const int jl0  = q * 2;               // 2 jh per thread
    const int jh0  = nt * 16 + jl0;
    const float lbv = __ldg(linb);

    float creg[2];                        // cell state lives in registers
    creg[0] = 0.0f; creg[1] = 0.0f;

    for (int t = 0; t < TTOT; ++t) {
        if (t == TENC) {
            load_w(whiD, wloD);
            Wih = decWih; bias = decB;
        }
        const __nv_bfloat16* hi = (t & 1) ? g_hhi1 : g_hhi0;
        const __nv_bfloat16* lo = (t & 1) ? g_hlo1 : g_hlo0;
        __nv_bfloat16* hio = (t & 1) ? g_hhi0 : g_hhi1;
        __nv_bfloat16* loo = (t & 1) ? g_hlo0 : g_hlo1;

        float acc[2][4];
#pragma unroll
        for (int ni = 0; ni < 2; ni++)
#pragma unroll
            for (int qq = 0; qq < 4; qq++) acc[ni][qq] = 0.0f;

        auto issue_pair = [&](int p) {
            const uint32_t ab = sb + (uint32_t)(p % 3) * ASTAGE_BYTES;
            const size_t go = (size_t)(brow0 + gr) * 512 + p * 64 + gce;
            cp16(ab + soA,          hi + go);
            cp16(ab + 16384u + soA, lo + go);
            cp_commit();
        };

        auto compute_pair = [&](int p) {
            const uint32_t ab  = sb + (uint32_t)(p % 3) * ASTAGE_BYTES;
            const uint32_t alb = ab + 16384u;
            const uint32_t whb = sb + WOFF + (uint32_t)p * 8192u;
            const uint32_t wlb = whb + 65536u;
#pragma unroll
            for (int s = 0; s < 4; ++s) {
                const uint32_t kb = (uint32_t)(s * 32);
                uint32_t ah[4], al[4];
                {
                    const uint32_t off = aoff + ((kb + kb2) ^ axor);
                    ldsm_x4(ah[0], ah[1], ah[2], ah[3], ab  + off);
                    ldsm_x4(al[0], al[1], al[2], al[3], alb + off);
                }
                uint32_t bh[2][2], bl[2][2];
                {
                    const uint32_t off = boff + ((kb + kb2) ^ bxor);
                    uint32_t q0, q1, q2, q3;
                    ldsm_x4(q0, q1, q2, q3, whb + off);
                    bh[0][0] = q0; bh[0][1] = q2;
                    bh[1][0] = q1; bh[1][1] = q3;
                    ldsm_x4(q0, q1, q2, q3, wlb + off);
                    bl[0][0] = q0; bl[0][1] = q2;
                    bl[1][0] = q1; bl[1][1] = q3;
                }
#pragma unroll
                for (int ni = 0; ni < 2; ++ni) {
                    mma_bf16(acc[ni], ah, bh[ni][0], bh[ni][1]);
                    mma_bf16(acc[ni], ah, bl[ni][0], bl[ni][1]);
                    mma_bf16(acc[ni], al, bh[ni][0], bh[ni][1]);
                }
            }
        };

        // pipeline: 8 pairs, 3 stages
        issue_pair(0);
        issue_pair(1);
        for (int p = 0; p < 8; ++p) {
            cp_wait1();
            __syncthreads();
            if (p + 2 < 8) issue_pair(p + 2);
            else           cp_commit();       // keep group count advancing
            compute_pair(p);
        }
        cp_wait0();
        __syncthreads();   // all compute done before zs overwrites stages 0-1

        // ---- accum -> zs (stride 68) -----------------------------------------
        {
            const int g  = lane >> 2;
            const int t2 = (lane & 3) * 2;
#pragma unroll
            for (int ni = 0; ni < 2; ni++) {
                const int row = wm * 16 + g;
                const int col = wn * 16 + ni * 8 + t2;
                *(float2*)(zs + row * 68 + col) = make_float2(acc[ni][0], acc[ni][1]);
                *(float2*)(zs + (row + 8) * 68 + col) = make_float2(acc[ni][2], acc[ni][3]);
            }
        }
        __syncthreads();

        // ---- gate pass: one row x 2 jh per thread -------------------------------
        {
            const int r = eml;
            const int b = brow0 + r;

            float xv;
            if (t < TENC) {
                xv = __ldg(inputs + (size_t)b * 512 + t);
            } else if (t == TENC) {
                xv = __ldg(inputs + (size_t)b * 512 + 511);
            } else {
                float s = 0.0f;
#pragma unroll
                for (int i = 0; i < 4; ++i)
                    s += g_xpart[(q * 4 + i) * B + b];
                s += __shfl_xor_sync(0xffffffffu, s, 1);
                s += __shfl_xor_sync(0xffffffffu, s, 2);
                s += __shfl_xor_sync(0xffffffffu, s, 4);
                xv = s + lbv;
                if (nt == 0 && q == 0)
                    out[(size_t)b * TDEC + (t - TENC - 1)] = xv;
            }

            const float2 wi0 = __ldg((const float2*)(Wih + jh0));
            const float2 wi1 = __ldg((const float2*)(Wih + 512 + jh0));
            const float2 wi2 = __ldg((const float2*)(Wih + 1024 + jh0));
            const float2 wi3 = __ldg((const float2*)(Wih + 1536 + jh0));
            const float2 bq0 = __ldg((const float2*)(bias + jh0));
            const float2 bq1 = __ldg((const float2*)(bias + 512 + jh0));
            const float2 bq2 = __ldg((const float2*)(bias + 1024 + jh0));
            const float2 bq3 = __ldg((const float2*)(bias + 1536 + jh0));

            const float2 zi = *(const float2*)(zs + r * 68 +      jl0);
            const float2 zf = *(const float2*)(zs + r * 68 + 16 + jl0);
            const float2 zg = *(const float2*)(zs + r * 68 + 32 + jl0);
            const float2 zo = *(const float2*)(zs + r * 68 + 48 + jl0);

            float hv[2];
            {
                const float vi0 = zi.x + xv * wi0.x + bq0.x;
                const float vf0 = zf.x + xv * wi1.x + bq1.x;
                const float vg0 = zg.x + xv * wi2.x + bq2.x;
                const float vo0 = zo.x + xv * wi3.x + bq3.x;
                const float cn0 = sigf(vf0) * creg[0] + sigf(vi0) * tanhe(vg0);
                creg[0] = cn0;
                hv[0] = sigf(vo0) * tanhe(cn0);

                const float vi1 = zi.y + xv * wi0.y + bq0.y;
                const float vf1 = zf.y + xv * wi1.y + bq1.y;
                const float vg1 = zg.y + xv * wi2.y + bq2.y;
                const float vo1 = zo.y + xv * wi3.y + bq3.y;
                const float cn1 = sigf(vf1) * creg[1] + sigf(vi1) * tanhe(vg1);
                creg[1] = cn1;
                hv[1] = sigf(vo1) * tanhe(cn1);
            }

            __nv_bfloat162 hh = __floats2bfloat162_rn(hv[0], hv[1]);
            float l0 = hv[0] - __bfloat162float(__low2bfloat16(hh));
            float l1 = hv[1] - __bfloat162float(__high2bfloat16(hh));
            __nv_bfloat162 hl = __floats2bfloat162_rn(l0, l1);
            const size_t oidx = (size_t)b * H + jh0;
            *(uint32_t*)(hio + oidx) = *(uint32_t*)&hh;
            *(uint32_t*)(loo + oidx) = *(uint32_t*)&hl;

            if (t >= TENC) {   // partial lin(h_t) for the next step's x
                const float2 lw2 = __ldg((const float2*)(linW + jh0));
                float s = hv[0] * lw2.x + hv[1] * lw2.y;
                s += __shfl_xor_sync(0xffffffffu, s, 1);
                s += __shfl_xor_sync(0xffffffffu, s, 2);
                s += __shfl_xor_sync(0xffffffffu, s, 4);
                if (q == 0) g_xpart[nt * B + b] = s;
            }
        }

        group_barrier(mt, (unsigned)((t + 1) & 1));
    }

    // ---- final output column: out[:, 127] = lin(h_final) -----------------------
    if (nt == 0 && tid < 128) {
        const int b = brow0 + tid;
        float s = lbv;
#pragma unroll
        for (int i = 0; i < 32; ++i) s += g_xpart[i * B + b];
        out[(size_t)b * TDEC + (TDEC - 1)] = s;
    }
}

// ---------------- launch ------------------------------------------------------
extern "C" void kernel_launch(void* const* d_in, const int* in_sizes, int n_in,
                              void* d_out, int out_size)
{
    (void)in_sizes; (void)n_in; (void)out_size;
    const float* inputs = (const float*)d_in[0];
    // d_in[1] = targets (unused: teacher_forcing_ratio == 0)
    const float* encWih = (const float*)d_in[2];
    const float* encWhh = (const float*)d_in[3];
    const float* encB   = (const float*)d_in[4];
    const float* decWih = (const float*)d_in[5];
    const float* decWhh = (const float*)d_in[6];
    const float* decB   = (const float*)d_in[7];
    const float* linW   = (const float*)d_in[8];
    const float* linB   = (const float*)d_in[9];
    float* out = (float*)d_out;

    cudaFuncSetAttribute(lstm_persistent,
                         cudaFuncAttributeMaxDynamicSharedMemorySize, SMEM_DYN);

    __nv_bfloat16 *whiE, *wloE, *whiD, *wloD;
    cudaGetSymbolAddress((void**)&whiE, g_whi_e);
    cudaGetSymbolAddress((void**)&wloE, g_wlo_e);
    cudaGetSymbolAddress((void**)&whiD, g_whi_d);
    cudaGetSymbolAddress((void**)&wloD, g_wlo_d);

    pack_w_kernel<<<4096, 256>>>(encWhh, whiE, wloE);
    pack_w_kernel<<<4096, 256>>>(decWhh, whiD, wloD);
    zero_state_kernel<<<(B * H) / 256, 256>>>();

    lstm_persistent<<<dim3(32, 4), NTHREADS, SMEM_DYN>>>(
        inputs, whiE, wloE, whiD, wloD,
        encWih, encB, decWih, decB, linW, linB, out);
}